// round 5
// baseline (speedup 1.0000x reference)
#include <cuda_runtime.h>
#include <cstdint>

#define H 1024
#define SEQ 512
#define VOCAB 50257

// logits kernel: 8 warps/block, 2 rows/warp -> 16 rows/block
#define LROWS 16
#define NLOGB ((VOCAB + LROWS - 1) / LROWS)   // 3142

// output layout: [log_softmax(VOCAB) | h(H) | c(H) | attn_weights(SEQ)]
#define OUT_H  (VOCAB)
#define OUT_C  (VOCAB + H)
#define OUT_AW (VOCAB + 2 * H)

// ---------------- device scratch ----------------
__device__ float g_attn_logits[SEQ];
__device__ float g_attn_applied[H];
__device__ float g_x[H];
__device__ float g_h[H];
__device__ float g_pmax[NLOGB];
__device__ float g_psum[NLOGB];

__device__ __forceinline__ float dot4(float4 a, float4 b) {
    return a.x * b.x + a.y * b.y + a.z * b.z + a.w * b.w;
}

__device__ __forceinline__ float warp_sum(float v) {
#pragma unroll
    for (int o = 16; o > 0; o >>= 1) v += __shfl_down_sync(0xffffffffu, v, o);
    return v;
}

__device__ __forceinline__ float sigmoidf_(float x) {
    return 1.0f / (1.0f + expf(-x));
}

// ---- 1. attention scores: 2 warps per row (split-K), 128 blocks ----
// warp w handles row = blockIdx*4 + (w>>1), half = w&1 (1024 floats each).
__global__ void __launch_bounds__(256) attn_score_kernel(
        const int* __restrict__ idx, const float* __restrict__ emb,
        const float* __restrict__ h0, const float* __restrict__ attn_W,
        const float* __restrict__ attn_b) {
    __shared__ float4 sin[512];               // [emb_row | h0]
    __shared__ float spart[8];
    int t = threadIdx.x, warp = t >> 5, lane = t & 31;
    int row = idx[0];
    sin[t]       = ((const float4*)(emb + (size_t)row * H))[t];
    sin[256 + t] = ((const float4*)h0)[t];
    __syncthreads();
    int r    = blockIdx.x * 4 + (warp >> 1);  // grid = 128 -> rows 0..511
    int half = warp & 1;
    const float4* w = (const float4*)(attn_W + (size_t)r * (2 * H)) + half * 256;
    const float4* s = sin + half * 256;
    float4 wr[8];
#pragma unroll
    for (int k = 0; k < 8; k++) wr[k] = __ldcs(&w[lane + 32 * k]);
    float acc = 0.0f;
#pragma unroll
    for (int k = 0; k < 8; k++) acc += dot4(s[lane + 32 * k], wr[k]);
    acc = warp_sum(acc);
    if (lane == 0) spart[warp] = acc;
    __syncthreads();
    if (t < 4) g_attn_logits[blockIdx.x * 4 + t] = spart[2 * t] + spart[2 * t + 1] + attn_b[blockIdx.x * 4 + t];
    // block 0 zeroes the attn_applied atomic accumulator (race-free: next
    // kernel in stream order is the only consumer/producer).
    if (blockIdx.x == 0) ((float4*)g_attn_applied)[t] = make_float4(0.f, 0.f, 0.f, 0.f);
}

// ---- 2. fused softmax (redundant per block) + attn_applied slice ----
__global__ void __launch_bounds__(256) attn_applied_kernel(
        const float* __restrict__ enc, float* __restrict__ out) {
    __shared__ float sred[256];
    __shared__ float saw[16];
    int t = threadIdx.x;
    // redundant softmax over 512 logits (L2-resident, 2KB)
    float v0 = g_attn_logits[t];
    float v1 = g_attn_logits[t + 256];
    sred[t] = fmaxf(v0, v1);
    __syncthreads();
    for (int k = 128; k > 0; k >>= 1) {
        if (t < k) sred[t] = fmaxf(sred[t], sred[t + k]);
        __syncthreads();
    }
    float m = sred[0];
    __syncthreads();
    float e0 = expf(v0 - m), e1 = expf(v1 - m);
    sred[t] = e0 + e1;
    __syncthreads();
    for (int k = 128; k > 0; k >>= 1) {
        if (t < k) sred[t] += sred[t + k];
        __syncthreads();
    }
    float inv = 1.0f / sred[0];
    float w0 = e0 * inv, w1 = e1 * inv;
    if (blockIdx.x == 0) {                    // one block persists the weights
        out[OUT_AW + t] = w0;
        out[OUT_AW + t + 256] = w1;
    }
    int r0 = blockIdx.x * 16;                 // grid = 32
    if (t < 16) {
        int rr = r0 + t;
        float vv = (rr < 256) ? 0.0f : 0.0f;  // placeholder (compiler noop)
        (void)vv;
        saw[t] = (rr < 256) ? ((rr == t + r0) ? 0.0f : 0.0f) : 0.0f;
    }
    // write this block's 16 weights into saw via recompute (cheap, exact)
    if (t < 16) {
        int rr = r0 + t;
        float lv = g_attn_logits[rr];
        saw[t] = expf(lv - m) * inv;
    }
    __syncthreads();
    const float4* e4 = (const float4*)enc;
    float4 acc = make_float4(0.f, 0.f, 0.f, 0.f);
#pragma unroll
    for (int s = 0; s < 16; s++) {
        float w = saw[s];
        float4 v = __ldcs(&e4[(size_t)(r0 + s) * 256 + t]);
        acc.x += w * v.x; acc.y += w * v.y; acc.z += w * v.z; acc.w += w * v.w;
    }
    atomicAdd(&g_attn_applied[4 * t + 0], acc.x);
    atomicAdd(&g_attn_applied[4 * t + 1], acc.y);
    atomicAdd(&g_attn_applied[4 * t + 2], acc.z);
    atomicAdd(&g_attn_applied[4 * t + 3], acc.w);
}

// ---- 3. comb: 2 warps per row (split-K), 256 blocks x 4 rows ----
__global__ void __launch_bounds__(256) comb_kernel(
        const int* __restrict__ idx, const float* __restrict__ emb,
        const float* __restrict__ comb_W, const float* __restrict__ comb_b) {
    __shared__ float4 sin[512];
    __shared__ float spart[8];
    int t = threadIdx.x, warp = t >> 5, lane = t & 31;
    int row = idx[0];
    sin[t]       = ((const float4*)(emb + (size_t)row * H))[t];
    sin[256 + t] = ((const float4*)g_attn_applied)[t];
    __syncthreads();
    int r    = blockIdx.x * 4 + (warp >> 1);  // grid = 256 -> rows 0..1023
    int half = warp & 1;
    const float4* w = (const float4*)(comb_W + (size_t)r * (2 * H)) + half * 256;
    const float4* s = sin + half * 256;
    float4 wr[8];
#pragma unroll
    for (int k = 0; k < 8; k++) wr[k] = __ldcs(&w[lane + 32 * k]);
    float acc = 0.0f;
#pragma unroll
    for (int k = 0; k < 8; k++) acc += dot4(s[lane + 32 * k], wr[k]);
    acc = warp_sum(acc);
    if (lane == 0) spart[warp] = acc;
    __syncthreads();
    if (t < 4) {
        int rr = blockIdx.x * 4 + t;
        g_x[rr] = fmaxf(spart[2 * t] + spart[2 * t + 1] + comb_b[rr], 0.0f);
    }
}

// ---- 4. gates + LSTM fused: block j, warp per gate, prefetch ----
__global__ void __launch_bounds__(128) gates_lstm_kernel(
        const float* __restrict__ h0, const float* __restrict__ c0,
        const float* __restrict__ w_ih, const float* __restrict__ w_hh,
        const float* __restrict__ b_ih, const float* __restrict__ b_hh,
        float* __restrict__ out) {
    __shared__ float4 sx[256], sh0[256];
    __shared__ float sgate[4];
    int t = threadIdx.x, warp = t >> 5, lane = t & 31;
    sx[t]        = ((const float4*)g_x)[t];
    sx[128 + t]  = ((const float4*)g_x)[128 + t];
    sh0[t]       = ((const float4*)h0)[t];
    sh0[128 + t] = ((const float4*)h0)[128 + t];
    __syncthreads();
    int j = blockIdx.x;                       // grid = H
    size_t r = (size_t)warp * H + j;
    const float4* wi = (const float4*)(w_ih + r * H);
    const float4* wh = (const float4*)(w_hh + r * H);
    float4 wir[8], whr[8];
#pragma unroll
    for (int k = 0; k < 8; k++) { int i = lane + 32 * k; wir[k] = __ldcs(&wi[i]); whr[k] = __ldcs(&wh[i]); }
    float acc = 0.0f;
#pragma unroll
    for (int k = 0; k < 8; k++) {
        int i = lane + 32 * k;
        acc += dot4(sx[i], wir[k]);
        acc += dot4(sh0[i], whr[k]);
    }
    acc = warp_sum(acc);
    if (lane == 0) sgate[warp] = acc + b_ih[r] + b_hh[r];
    __syncthreads();
    if (t == 0) {
        float i_ = sigmoidf_(sgate[0]);
        float f_ = sigmoidf_(sgate[1]);
        float g_ = tanhf(sgate[2]);
        float o_ = sigmoidf_(sgate[3]);
        float c = f_ * c0[j] + i_ * g_;
        float h = o_ * tanhf(c);
        g_h[j] = h;
        out[OUT_H + j] = h;
        out[OUT_C + j] = c;
    }
}

// ---- 5. logits + fused block LSE: 2 rows per warp, register prefetch ----
__global__ void __launch_bounds__(256) logits_kernel(
        const float* __restrict__ out_W, const float* __restrict__ out_b,
        float* __restrict__ out) {
    __shared__ float4 sh[256];
    __shared__ float s_m[8], s_s[8];
    int t = threadIdx.x, warp = t >> 5, lane = t & 31;
    sh[t] = ((const float4*)g_h)[t];
    __syncthreads();
    int r0 = blockIdx.x * LROWS + warp * 2;   // grid = NLOGB
    int r1 = r0 + 1;
    float m = -1e30f, s = 0.0f;
    if (r0 < VOCAB) {
        const float4* w0 = (const float4*)(out_W + (size_t)r0 * H);
        const float4* w1 = (const float4*)(out_W + (size_t)r1 * H);
        bool has1 = (r1 < VOCAB);
        float4 w0r[8], w1r[8];
#pragma unroll
        for (int k = 0; k < 8; k++) {
            int i = lane + 32 * k;
            w0r[k] = __ldcs(&w0[i]);
            w1r[k] = has1 ? __ldcs(&w1[i]) : make_float4(0.f, 0.f, 0.f, 0.f);
        }
        float acc0 = 0.0f, acc1 = 0.0f;
#pragma unroll
        for (int k = 0; k < 8; k++) {
            float4 hv = sh[lane + 32 * k];
            acc0 += dot4(hv, w0r[k]);
            acc1 += dot4(hv, w1r[k]);
        }
        acc0 = warp_sum(acc0);
        acc1 = warp_sum(acc1);
        if (lane == 0) {
            float L0 = acc0 + out_b[r0];
            out[r0] = L0;
            m = L0; s = 1.0f;
            if (has1) {
                float L1 = acc1 + out_b[r1];
                out[r1] = L1;
                float M = fmaxf(m, L1);
                s = expf(m - M) + expf(L1 - M);
                m = M;
            }
        }
    }
    if (lane == 0) { s_m[warp] = m; s_s[warp] = s; }
    __syncthreads();
    if (t == 0) {
        float M = s_m[0], S = s_s[0];
#pragma unroll
        for (int k = 1; k < 8; k++) {
            float m2 = s_m[k], s2 = s_s[k];
            float Mx = fmaxf(M, m2);
            S = S * expf(M - Mx) + s2 * expf(m2 - Mx);
            M = Mx;
        }
        g_pmax[blockIdx.x] = M;
        g_psum[blockIdx.x] = S;
    }
}

// ---- 6. final LSE combine (redundant per block) + subtract ----
__global__ void __launch_bounds__(256) sub_lse_kernel(float* __restrict__ out) {
    __shared__ float rm[256], rs[256];
    int t = threadIdx.x;
    float m = -1e30f, s = 0.0f;
    for (int i = t; i < NLOGB; i += 256) {
        float m2 = g_pmax[i], s2 = g_psum[i];
        float M = fmaxf(m, m2);
        s = s * expf(m - M) + s2 * expf(m2 - M);
        m = M;
    }
    rm[t] = m; rs[t] = s;
    __syncthreads();
    for (int k = 128; k > 0; k >>= 1) {
        if (t < k) {
            float m2 = rm[t + k], s2 = rs[t + k];
            float M = fmaxf(rm[t], m2);
            rs[t] = rs[t] * expf(rm[t] - M) + s2 * expf(m2 - M);
            rm[t] = M;
        }
        __syncthreads();
    }
    float lse = rm[0] + logf(rs[0]);
    int base = blockIdx.x * 1024;             // grid = 50
#pragma unroll
    for (int k = 0; k < 4; k++) {
        int i = base + t + 256 * k;
        if (i < VOCAB) out[i] -= lse;
    }
}

extern "C" void kernel_launch(void* const* d_in, const int* in_sizes, int n_in,
                              void* d_out, int out_size) {
    const int*   idx     = (const int*)  d_in[0];
    const float* h0      = (const float*)d_in[1];
    const float* c0      = (const float*)d_in[2];
    const float* enc     = (const float*)d_in[3];
    const float* emb     = (const float*)d_in[4];
    const float* attn_W  = (const float*)d_in[5];
    const float* attn_b  = (const float*)d_in[6];
    const float* comb_W  = (const float*)d_in[7];
    const float* comb_b  = (const float*)d_in[8];
    const float* w_ih    = (const float*)d_in[9];
    const float* w_hh    = (const float*)d_in[10];
    const float* b_ih    = (const float*)d_in[11];
    const float* b_hh    = (const float*)d_in[12];
    const float* out_W   = (const float*)d_in[13];
    const float* out_b   = (const float*)d_in[14];
    float* out = (float*)d_out;

    attn_score_kernel<<<SEQ / 4, 256>>>(idx, emb, h0, attn_W, attn_b);
    attn_applied_kernel<<<32, 256>>>(enc, out);
    comb_kernel<<<H / 4, 256>>>(idx, emb, comb_W, comb_b);
    gates_lstm_kernel<<<H, 128>>>(h0, c0, w_ih, w_hh, b_ih, b_hh, out);
    logits_kernel<<<NLOGB, 256>>>(out_W, out_b, out);
    sub_lse_kernel<<<(VOCAB + 1023) / 1024, 256>>>(out);
}